// round 5
// baseline (speedup 1.0000x reference)
#include <cuda_runtime.h>
#include <cuda_bf16.h>

// STDP collapses because TE=1: e_t = e_{t-1} - e_{t-1}/1 + (x_t q_t^T - p_t y_t^T)
//                                  = x_t q_t^T - p_t y_t^T    (decay term exactly 0)
// => final e = x_T ⊗ q_T - p_T ⊗ y_T, x/y the per-column filtered traces
//    x <- x + (p - x)*0.5 over T steps. Homogeneous part scales by exactly 0.5
//    per step, so contributions older than 128 steps are scaled by 2^-128 ~ 0:
//    only the last 128 timesteps matter (abs error < 6e-39).
//
// Single fused kernel: trace phase (64 blocks) -> atomic grid barrier ->
// outer-product phase (128 blocks). Grid = 128 blocks <= 148 SMs, so all
// blocks are co-resident (one wave) and the spin barrier cannot deadlock.
//
// Shapes fixed by the problem: T=256, N_PRE=N_POST=1024.

#define N_MAX 1024
#define NCHUNK 8
#define CHUNK 16
#define TRACE_COLS 32              // columns per trace block; NCHUNK*32 = 256 thr
#define ROWS_PER_BLOCK 8

__device__ float g_x[N_MAX];       // final pre-trace  x_T
__device__ float g_y[N_MAX];       // final post-trace y_T
__device__ int   g_count;          // trace-done arrivals (zero-init, reset per launch)
__device__ int   g_done;           // block-exit arrivals (zero-init, reset per launch)

__global__ void __launch_bounds__(256, 1)
stdp_fused_kernel(const float* __restrict__ pre,
                  const float* __restrict__ post,
                  float* __restrict__ out,
                  int T, int N)
{
    const int tid = threadIdx.x;
    const int bid = blockIdx.x;
    const int nTraceBlocks = (2 * N + TRACE_COLS - 1) / TRACE_COLS;   // 64

    // ---------------- Phase 1: traces (first 64 blocks) ----------------
    if (bid < nTraceBlocks) {
        int colLocal = tid & (TRACE_COLS - 1);
        int chunk    = tid / TRACE_COLS;                 // 0..7
        int gcol     = bid * TRACE_COLS + colLocal;      // 0..2N-1
        const float* src = (gcol < N) ? pre : post;
        int col = (gcol < N) ? gcol : gcol - N;

        int t0 = T - NCHUNK * CHUNK + chunk * CHUNK;     // last 128 steps
        float acc = 0.0f;
        #pragma unroll
        for (int k = 0; k < CHUNK; ++k) {
            int t = t0 + k;
            float s = (t >= 0) ? __ldg(&src[(size_t)t * N + col]) : 0.0f;
            acc = acc + (s - acc) * 0.5f;                // matches reference fp32 order
        }

        __shared__ float sb[NCHUNK][TRACE_COLS];
        sb[chunk][colLocal] = acc;
        __syncthreads();

        if (chunk == 0) {
            const float A = 1.52587890625e-05f;          // 2^-16, exact
            float x = sb[0][colLocal];
            #pragma unroll
            for (int c = 1; c < NCHUNK; ++c)
                x = x * A + sb[c][colLocal];
            if (gcol < N) __stcg(&g_x[col], x);          // write through to L2
            else          __stcg(&g_y[col], x);
            __threadfence();                             // make visible before arrive
        }
        __syncthreads();
        if (tid == 0) atomicAdd(&g_count, 1);
    }

    // ---------------- Grid barrier (all 128 blocks) ----------------
    if (tid == 0) {
        while (*((volatile int*)&g_count) < nTraceBlocks) { }
        __threadfence();
    }
    __syncthreads();

    // ---------------- Phase 2: out[i][j] = x[i]*q[j] - p[i]*y[j] ----------------
    const int N4   = N >> 2;
    const int row0 = bid * ROWS_PER_BLOCK;
    const float* preLast  = pre  + (size_t)(T - 1) * N;
    const float* postLast = post + (size_t)(T - 1) * N;

    float xi[ROWS_PER_BLOCK], pi[ROWS_PER_BLOCK];
    #pragma unroll
    for (int r = 0; r < ROWS_PER_BLOCK; ++r) {
        xi[r] = __ldcg(&g_x[row0 + r]);                  // L2-coherent read
        pi[r] = __ldg(&preLast[row0 + r]);
    }

    float4 q = reinterpret_cast<const float4*>(postLast)[tid];
    float4 y = __ldcg(&reinterpret_cast<const float4*>(g_y)[tid]);

    float4* o = reinterpret_cast<float4*>(out);
    #pragma unroll
    for (int r = 0; r < ROWS_PER_BLOCK; ++r) {
        float4 v;
        v.x = xi[r] * q.x - pi[r] * y.x;
        v.y = xi[r] * q.y - pi[r] * y.y;
        v.z = xi[r] * q.z - pi[r] * y.z;
        v.w = xi[r] * q.w - pi[r] * y.w;
        o[(size_t)(row0 + r) * N4 + tid] = v;
    }

    // ---------------- Counter reset for deterministic graph replay ----------------
    if (tid == 0) {
        int d = atomicAdd(&g_done, 1);
        if (d == (int)gridDim.x - 1) {                   // last block out resets
            atomicExch(&g_count, 0);
            atomicExch(&g_done, 0);
        }
    }
}

extern "C" void kernel_launch(void* const* d_in, const int* in_sizes, int n_in,
                              void* d_out, int out_size)
{
    const float* pre  = (const float*)d_in[0];   // [T, N_pre]
    const float* post = (const float*)d_in[1];   // [T, N_post]
    float* out = (float*)d_out;                  // [N_pre, N_post]

    int N = 1;
    while ((long long)N * N < (long long)out_size) N <<= 1;   // -> 1024
    int T = in_sizes[0] / N;                                   // -> 256

    // 128 blocks (one wave on 148 SMs), 256 threads each.
    stdp_fused_kernel<<<N / ROWS_PER_BLOCK, 256>>>(pre, post, out, T, N);
}

// round 9
// speedup vs baseline: 1.2917x; 1.2917x over previous
#include <cuda_runtime.h>
#include <cuda_bf16.h>

// STDP collapses because TE=1:
//   e_t = e_{t-1} - e_{t-1}/1 + (x_t q_t^T - p_t y_t^T) = x_t q_t^T - p_t y_t^T
// (the decay term is exactly zero), so the output is just the LAST timestep's
// rank-2 outer product, with x,y the per-column filtered traces
//   x <- x + (p - x)*0.5.
// The homogeneous part scales by exactly 0.5/step, so a 32-step horizon is
// exact to 2^-32 (~2.3e-10 abs) — cheap enough to recompute PER BLOCK,
// removing all inter-block dependencies (no second kernel, no grid barrier).
//
// One launch: 128 blocks = 16x8 tiles of 64 rows x 128 cols.
//   Phase A: threads 0..63 -> x-trace for 64 tile rows,
//            threads 64..191 -> y-trace for 128 tile cols  (32 steps each)
//   Phase B: tile outer product from smem, 8 float4 stores per thread.
//
// Shapes fixed by the problem: T=256, N_PRE=N_POST=1024.

#define HORIZON 32
#define TILE_R  64
#define TILE_C  128

__global__ void __launch_bounds__(256, 1)
stdp_tile_kernel(const float* __restrict__ pre,
                 const float* __restrict__ post,
                 float* __restrict__ out,
                 int T, int N)
{
    const int tid = threadIdx.x;
    const int bc  = blockIdx.x & 7;          // 8 column tiles
    const int br  = blockIdx.x >> 3;         // 16 row tiles
    const int r0  = br * TILE_R;
    const int c0  = bc * TILE_C;

    __shared__ float sx[TILE_R], sp[TILE_R];   // x-trace, last pre row
    __shared__ float sy[TILE_C], sq[TILE_C];   // y-trace, last post row

    // ---------------- Phase A: 32-step traces for this tile ----------------
    if (tid < TILE_R + TILE_C) {
        const bool isRow = tid < TILE_R;
        const float* src = isRow ? pre : post;
        const int col    = isRow ? (r0 + tid) : (c0 + tid - TILE_R);

        const float* base = src + (size_t)(T - HORIZON) * N + col;
        float acc = 0.0f;
        float last = 0.0f;
        #pragma unroll
        for (int k = 0; k < HORIZON; ++k) {
            float s = __ldg(base + (size_t)k * N);   // 32 independent loads, batched
            acc = acc + (s - acc) * 0.5f;            // reference fp32 op order
            last = s;                                 // s at k=HORIZON-1 = input[T-1]
        }
        if (isRow) { sx[tid] = acc;            sp[tid] = last; }
        else       { sy[tid - TILE_R] = acc;   sq[tid - TILE_R] = last; }
    }
    __syncthreads();

    // ---------------- Phase B: tile of out[i][j] = x_i q_j - p_i y_j ----------------
    // Thread layout: colGroup = tid % 32 (4 cols each), rowBase = tid / 32,
    // rows rowBase, rowBase+8, ..., rowBase+56  (8 rows per thread).
    const int cg   = tid & 31;       // 0..31 -> columns c0 + 4*cg .. +3
    const int rb   = tid >> 5;       // 0..7
    const int N4   = N >> 2;

    float4 y4 = reinterpret_cast<const float4*>(sy)[cg];
    float4 q4 = reinterpret_cast<const float4*>(sq)[cg];

    float4* o = reinterpret_cast<float4*>(out);
    #pragma unroll
    for (int r = 0; r < 8; ++r) {
        int lr = rb + r * 8;                 // local row 0..63
        float xi = sx[lr];                   // broadcast across the warp
        float pi = sp[lr];
        float4 v;
        v.x = xi * q4.x - pi * y4.x;
        v.y = xi * q4.y - pi * y4.y;
        v.z = xi * q4.z - pi * y4.z;
        v.w = xi * q4.w - pi * y4.w;
        o[(size_t)(r0 + lr) * N4 + (c0 >> 2) + cg] = v;
    }
}

extern "C" void kernel_launch(void* const* d_in, const int* in_sizes, int n_in,
                              void* d_out, int out_size)
{
    const float* pre  = (const float*)d_in[0];   // [T, N_pre]
    const float* post = (const float*)d_in[1];   // [T, N_post]
    float* out = (float*)d_out;                  // [N_pre, N_post]

    int N = 1;
    while ((long long)N * N < (long long)out_size) N <<= 1;   // -> 1024
    int T = in_sizes[0] / N;                                   // -> 256

    // 128 independent blocks (one wave), 256 threads each, no cross-block deps.
    int grid = (N / TILE_R) * (N / TILE_C);                    // 16*8 = 128
    stdp_tile_kernel<<<grid, 256>>>(pre, post, out, T, N);
}

// round 12
// speedup vs baseline: 1.3037x; 1.0093x over previous
#include <cuda_runtime.h>
#include <cuda_bf16.h>

// STDP collapses because TE=1:
//   e_t = e_{t-1} - e_{t-1}/1 + (x_t q_t^T - p_t y_t^T) = x_t q_t^T - p_t y_t^T
// (the decay term is exactly zero), so the output is the LAST timestep's
// rank-2 outer product, with x,y the per-column filtered traces
//   x <- x + (p - x)*0.5.
// The homogeneous part scales by exactly 0.5/step: a 24-step horizon is exact
// to 2^-24 (~6e-8 abs) — cheap enough to recompute PER BLOCK, so there are no
// inter-block dependencies (single launch, no grid barrier).
//
// 128 blocks = 16x8 tiles of 64 rows x 128 cols, 256 threads each:
//   entry:   Phase-B gmem operands (last pre/post rows) are loaded FIRST so
//            their DRAM latency overlaps the trace chains.
//   Phase A: threads 0..63 -> x-trace for the tile's 64 rows,
//            threads 64..191 -> y-trace for its 128 cols (24 steps each).
//   Phase B: tile outer product, 8 float4 coalesced stores per thread.
//
// Shapes fixed by the problem: T=256, N_PRE=N_POST=1024.

#define HORIZON 24
#define TILE_R  64
#define TILE_C  128

__global__ void __launch_bounds__(256, 1)
stdp_tile_kernel(const float* __restrict__ pre,
                 const float* __restrict__ post,
                 float* __restrict__ out,
                 int T, int N)
{
    const int tid = threadIdx.x;
    const int bc  = blockIdx.x & 7;          // 8 column tiles
    const int br  = blockIdx.x >> 3;         // 16 row tiles
    const int r0  = br * TILE_R;
    const int c0  = bc * TILE_C;

    __shared__ float sx[TILE_R];             // x-trace for tile rows
    __shared__ float sy[TILE_C];             // y-trace for tile cols

    // ---- Issue Phase-B global loads FIRST (independent of the traces) ----
    const int cg = tid & 31;                 // 0..31 -> 4 cols each
    const int rb = tid >> 5;                 // 0..7  -> rows rb, rb+8, ..., rb+56
    const float* preLast  = pre  + (size_t)(T - 1) * N;
    const float* postLast = post + (size_t)(T - 1) * N;

    float4 q4 = __ldg(&reinterpret_cast<const float4*>(postLast + c0)[cg]);
    float  pi[8];
    #pragma unroll
    for (int r = 0; r < 8; ++r)
        pi[r] = __ldg(&preLast[r0 + rb + r * 8]);

    // ---------------- Phase A: 24-step traces for this tile ----------------
    if (tid < TILE_R + TILE_C) {
        const bool isRow = tid < TILE_R;
        const float* src = isRow ? pre : post;
        const int col    = isRow ? (r0 + tid) : (c0 + tid - TILE_R);

        const float* base = src + (size_t)(T - HORIZON) * N + col;
        float acc = 0.0f;
        #pragma unroll
        for (int k = 0; k < HORIZON; ++k) {
            float s = __ldg(base + (size_t)k * N);   // independent loads, batched
            acc = acc + (s - acc) * 0.5f;            // reference fp32 op order
        }
        if (isRow) sx[tid] = acc;
        else       sy[tid - TILE_R] = acc;
    }
    __syncthreads();

    // ---------------- Phase B: out[i][j] = x_i q_j - p_i y_j ----------------
    const int N4 = N >> 2;
    float4 y4 = reinterpret_cast<const float4*>(sy)[cg];

    float4* o = reinterpret_cast<float4*>(out);
    #pragma unroll
    for (int r = 0; r < 8; ++r) {
        int lr = rb + r * 8;                 // local row 0..63
        float xi = sx[lr];                   // smem broadcast across the warp
        float4 v;
        v.x = xi * q4.x - pi[r] * y4.x;
        v.y = xi * q4.y - pi[r] * y4.y;
        v.z = xi * q4.z - pi[r] * y4.z;
        v.w = xi * q4.w - pi[r] * y4.w;
        o[(size_t)(r0 + lr) * N4 + (c0 >> 2) + cg] = v;
    }
}

extern "C" void kernel_launch(void* const* d_in, const int* in_sizes, int n_in,
                              void* d_out, int out_size)
{
    const float* pre  = (const float*)d_in[0];   // [T, N_pre]
    const float* post = (const float*)d_in[1];   // [T, N_post]
    float* out = (float*)d_out;                  // [N_pre, N_post]

    int N = 1;
    while ((long long)N * N < (long long)out_size) N <<= 1;   // -> 1024
    int T = in_sizes[0] / N;                                   // -> 256

    // 128 independent blocks (single wave), 256 threads, no cross-block deps.
    int grid = (N / TILE_R) * (N / TILE_C);                    // 16*8 = 128
    stdp_tile_kernel<<<grid, 256>>>(pre, post, out, T, N);
}